// round 1
// baseline (speedup 1.0000x reference)
#include <cuda_runtime.h>

#define I_DIM 2048
#define H_DIM 96
#define B_DIM 64
#define T_DIM 512

typedef unsigned long long ull;

__device__ __forceinline__ void fma2(ull &d, ull a, ull b) {
    asm("fma.rn.f32x2 %0, %1, %2, %0;" : "+l"(d) : "l"(a), "l"(b));
}
__device__ __forceinline__ ull pack2(float lo, float hi) {
    ull v; asm("mov.b64 %0, {%1, %2};" : "=l"(v) : "f"(lo), "f"(hi)); return v;
}
__device__ __forceinline__ float hadd2(ull v) {
    float lo, hi; asm("mov.b64 {%0, %1}, %2;" : "=f"(lo), "=f"(hi) : "l"(v)); return lo + hi;
}

// Scratch: layer-0 input projection, [B*T, 96]
__device__ float g_xproj[(size_t)B_DIM * T_DIM * H_DIM];

// ---------------------------------------------------------------------------
// Kernel 1: xproj0 = x @ w_ih0^T + b_ih0
// C[M=32768, N=96] = X[M, K=2048] * W[96, 2048]^T, fp32 with packed f32x2 FMA.
// CTA tile: 128 rows x 96 cols, K-chunks of 32. 256 threads, each 8m x 6n.
// ---------------------------------------------------------------------------
__global__ __launch_bounds__(256) void xproj_gemm(const float* __restrict__ X,
                                                  const float* __restrict__ W,
                                                  const float* __restrict__ bias)
{
    __shared__ __align__(16) float  Xs[32][130];   // [k][m], padded
    __shared__ __align__(8)  float2 Ws[32][96];    // [k][n], duplicated {w,w}

    const int tid = threadIdx.x;
    const int tn = tid & 15, tm = tid >> 4;
    const int m0 = tm * 8, n0 = tn * 6;
    const int rowbase = blockIdx.x * 128;

    ull acc[4][6];
    #pragma unroll
    for (int i = 0; i < 4; i++)
        #pragma unroll
        for (int j = 0; j < 6; j++) acc[i][j] = 0ull;

    for (int k0 = 0; k0 < I_DIM; k0 += 32) {
        // Load X chunk (128 rows x 32 cols) transposed into Xs[k][m]
        #pragma unroll
        for (int i = 0; i < 4; i++) {
            int f = tid + i * 256;           // 0..1023
            int r = f >> 3;                  // row 0..127
            int c4 = (f & 7) * 4;            // col 0..28
            float4 v = *(const float4*)(X + (size_t)(rowbase + r) * I_DIM + k0 + c4);
            Xs[c4 + 0][r] = v.x;
            Xs[c4 + 1][r] = v.y;
            Xs[c4 + 2][r] = v.z;
            Xs[c4 + 3][r] = v.w;
        }
        // Load W chunk (96 rows x 32 cols) into Ws[k][n] duplicated
        #pragma unroll
        for (int i = 0; i < 12; i++) {
            int f = tid + i * 256;           // 0..3071
            int n = f >> 5, kl = f & 31;
            float w = W[(size_t)n * I_DIM + k0 + kl];
            Ws[kl][n] = make_float2(w, w);
        }
        __syncthreads();

        #pragma unroll 4
        for (int kk = 0; kk < 32; kk++) {
            ull a[4], wv[6];
            #pragma unroll
            for (int i = 0; i < 4; i++) a[i] = *(const ull*)&Xs[kk][m0 + 2 * i];
            #pragma unroll
            for (int jj = 0; jj < 6; jj++) wv[jj] = *(const ull*)&Ws[kk][n0 + jj];
            #pragma unroll
            for (int i = 0; i < 4; i++)
                #pragma unroll
                for (int jj = 0; jj < 6; jj++) fma2(acc[i][jj], a[i], wv[jj]);
        }
        __syncthreads();
    }

    #pragma unroll
    for (int jj = 0; jj < 6; jj++) {
        float bn = bias[n0 + jj];
        #pragma unroll
        for (int i = 0; i < 4; i++) {
            float lo, hi;
            asm("mov.b64 {%0, %1}, %2;" : "=f"(lo), "=f"(hi) : "l"(acc[i][jj]));
            size_t row = (size_t)rowbase + m0 + 2 * i;
            g_xproj[row * H_DIM + n0 + jj]       = lo + bn;
            g_xproj[(row + 1) * H_DIM + n0 + jj] = hi + bn;
        }
    }
}

// ---------------------------------------------------------------------------
// Kernel 2: recurrent scan, 1 CTA per batch element, 3-layer wavefront.
// 480 threads: [0,96)   layer0 (full K, output j)
//              [96,288) layer1 (j = local%96, half = local/96, split-K)
//              [288,480) layer2 (same split)
// Weights live in registers (48 x f32x2 per thread). h vectors in smem.
// Tick u: layer0 computes h0(u), layer1 h1(u-1), layer2 h2(u-2).
// ---------------------------------------------------------------------------
__global__ __launch_bounds__(480, 1) void rnn_scan(
    const float* __restrict__ whh0, const float* __restrict__ bhh0,
    const float* __restrict__ wih1, const float* __restrict__ whh1,
    const float* __restrict__ bih1, const float* __restrict__ bhh1,
    const float* __restrict__ wih2, const float* __restrict__ whh2,
    const float* __restrict__ bih2, const float* __restrict__ bhh2,
    const float* __restrict__ fcw,  const float* __restrict__ fcb,
    float* __restrict__ out)
{
    __shared__ __align__(16) float h0[2][96];
    __shared__ __align__(16) float h1[2][96];
    __shared__ __align__(16) float h2[2][96];
    __shared__ __align__(16) float p1[2][96];
    __shared__ __align__(16) float p2[2][96];
    __shared__ float sred[96];

    const int tid = threadIdx.x;
    const int b = blockIdx.x;

    if (tid < 96) {
        h0[0][tid] = 0.f; h0[1][tid] = 0.f;
        h1[0][tid] = 0.f; h1[1][tid] = 0.f;
        h2[0][tid] = 0.f; h2[1][tid] = 0.f;
    }

    // ---- load per-thread weights into registers ----
    ull wA[24], wB[24];
    float bias = 0.f;
    int role, j, half = 0, base = 0;
    if (tid < 96) {
        role = 0; j = tid;
        const float* r = whh0 + j * 96;
        #pragma unroll
        for (int q = 0; q < 24; q++) wA[q] = pack2(__ldg(r + 2 * q), __ldg(r + 2 * q + 1));
        #pragma unroll
        for (int q = 0; q < 24; q++) wB[q] = pack2(__ldg(r + 48 + 2 * q), __ldg(r + 48 + 2 * q + 1));
        bias = __ldg(bhh0 + j);
    } else if (tid < 288) {
        role = 1; int local = tid - 96;
        j = (local < 96) ? local : local - 96;
        half = (local < 96) ? 0 : 1;
        base = 48 * half;
        const float* ri = wih1 + j * 96 + base;
        const float* rh = whh1 + j * 96 + base;
        #pragma unroll
        for (int q = 0; q < 24; q++) wA[q] = pack2(__ldg(ri + 2 * q), __ldg(ri + 2 * q + 1));
        #pragma unroll
        for (int q = 0; q < 24; q++) wB[q] = pack2(__ldg(rh + 2 * q), __ldg(rh + 2 * q + 1));
        if (half == 0) bias = __ldg(bih1 + j) + __ldg(bhh1 + j);
    } else {
        role = 2; int local = tid - 288;
        j = (local < 96) ? local : local - 96;
        half = (local < 96) ? 0 : 1;
        base = 48 * half;
        const float* ri = wih2 + j * 96 + base;
        const float* rh = whh2 + j * 96 + base;
        #pragma unroll
        for (int q = 0; q < 24; q++) wA[q] = pack2(__ldg(ri + 2 * q), __ldg(ri + 2 * q + 1));
        #pragma unroll
        for (int q = 0; q < 24; q++) wB[q] = pack2(__ldg(rh + 2 * q), __ldg(rh + 2 * q + 1));
        if (half == 0) bias = __ldg(bih2 + j) + __ldg(bhh2 + j);
    }

    // xproj prefetch registers (depth 2), role 0 only
    const float* xpp = g_xproj + ((size_t)b * T_DIM) * H_DIM + j;
    float xp0 = 0.f, xp1 = 0.f;
    if (role == 0) { xp0 = xpp[0]; xp1 = xpp[96]; }

    __syncthreads();

    auto tick = [&](int u, float& xpr) {
        const int p = u & 1, q = p ^ 1;
        const float *sa, *sb;
        bool act;
        if (role == 0)      { act = (u < T_DIM);              sa = h0[q];        sb = h0[q] + 48;   }
        else if (role == 1) { act = (u >= 1 && u <= T_DIM);   sa = h0[q] + base; sb = h1[p] + base; }
        else                { act = (u >= 2 && u <= T_DIM+1); sa = h1[p] + base; sb = h2[q] + base; }

        if (act) {
            ull a0 = 0, a1 = 0, a2 = 0, a3 = 0;
            #pragma unroll
            for (int m = 0; m < 12; m++) {
                ulonglong2 va = *(const ulonglong2*)(sa + 4 * m);
                ulonglong2 vb = *(const ulonglong2*)(sb + 4 * m);
                fma2(a0, wA[2 * m],     va.x);
                fma2(a1, wA[2 * m + 1], va.y);
                fma2(a2, wB[2 * m],     vb.x);
                fma2(a3, wB[2 * m + 1], vb.y);
            }
            float s = (hadd2(a0) + hadd2(a1)) + (hadd2(a2) + hadd2(a3));
            if (role == 0) {
                h0[p][j] = tanhf(s + xpr + bias);
                if (u + 2 < T_DIM) xpr = xpp[(u + 2) * H_DIM];
            } else if (role == 1) {
                p1[half][j] = s;
            } else {
                p2[half][j] = s;
            }
        }
        __syncthreads();
        // combine split-K partials + activation (one thread-group per layer)
        if (tid >= 96 && tid < 192 && u >= 1 && u <= T_DIM)
            h1[q][j] = tanhf(p1[0][j] + p1[1][j] + bias);
        if (tid >= 288 && tid < 384 && u >= 2 && u <= T_DIM + 1)
            h2[p][j] = tanhf(p2[0][j] + p2[1][j] + bias);
        __syncthreads();
    };

    for (int u = 0; u < T_DIM + 2; u += 2) {
        tick(u, xp0);
        tick(u + 1, xp1);
    }

    // FC head: out[b] = h2(T-1) . fc_w + fc_b   (T-1 = 511 -> parity 1)
    if (tid < 96) sred[tid] = h2[1][tid] * __ldg(fcw + tid);
    __syncthreads();
    if (tid == 0) {
        float s = __ldg(fcb);
        #pragma unroll
        for (int k = 0; k < 96; k++) s += sred[k];
        out[b] = s;
    }
}

extern "C" void kernel_launch(void* const* d_in, const int* in_sizes, int n_in,
                              void* d_out, int out_size) {
    const float* x     = (const float*)d_in[0];
    const float* w_ih0 = (const float*)d_in[1];
    const float* w_hh0 = (const float*)d_in[2];
    const float* b_ih0 = (const float*)d_in[3];
    const float* b_hh0 = (const float*)d_in[4];
    const float* w_ih1 = (const float*)d_in[5];
    const float* w_hh1 = (const float*)d_in[6];
    const float* b_ih1 = (const float*)d_in[7];
    const float* b_hh1 = (const float*)d_in[8];
    const float* w_ih2 = (const float*)d_in[9];
    const float* w_hh2 = (const float*)d_in[10];
    const float* b_ih2 = (const float*)d_in[11];
    const float* b_hh2 = (const float*)d_in[12];
    const float* fc_w  = (const float*)d_in[13];
    const float* fc_b  = (const float*)d_in[14];
    float* out = (float*)d_out;

    xproj_gemm<<<(B_DIM * T_DIM) / 128, 256>>>(x, w_ih0, b_ih0);
    rnn_scan<<<B_DIM, 480>>>(w_hh0, b_hh0,
                             w_ih1, w_hh1, b_ih1, b_hh1,
                             w_ih2, w_hh2, b_ih2, b_hh2,
                             fc_w, fc_b, out);
}

// round 3
// speedup vs baseline: 1.9189x; 1.9189x over previous
#include <cuda_runtime.h>
#include <cuda_bf16.h>
#include <cstdint>

#define I_DIM 2048
#define H_DIM 96
#define B_DIM 64
#define T_DIM 512

typedef unsigned long long ull;

// ============================ generic helpers ==============================

__device__ __forceinline__ void fma2(ull &d, ull a, ull b) {
    asm("fma.rn.f32x2 %0, %1, %2, %0;" : "+l"(d) : "l"(a), "l"(b));
}
__device__ __forceinline__ ull pack2(float lo, float hi) {
    ull v; asm("mov.b64 %0, {%1, %2};" : "=l"(v) : "f"(lo), "f"(hi)); return v;
}
__device__ __forceinline__ float hadd2(ull v) {
    float lo, hi; asm("mov.b64 {%0, %1}, %2;" : "=f"(lo), "=f"(hi) : "l"(v)); return lo + hi;
}
// branch-free tanh: 1 - 2/(e^{2x}+1); exact limits, ~1e-6 rel err.
__device__ __forceinline__ float fast_tanh(float x) {
    float e = __expf(2.0f * x);
    return 1.0f - __fdividef(2.0f, e + 1.0f);
}
__device__ __forceinline__ uint32_t smem_u32(const void* p) {
    uint32_t a;
    asm("{ .reg .u64 t; cvta.to.shared.u64 t, %1; cvt.u32.u64 %0, t; }" : "=r"(a) : "l"(p));
    return a;
}

// ======================= mma.sync / ldmatrix helpers =======================

__device__ __forceinline__ void ldsm_x4(uint32_t &r0, uint32_t &r1, uint32_t &r2,
                                        uint32_t &r3, uint32_t addr) {
    asm volatile("ldmatrix.sync.aligned.m8n8.x4.shared.b16 {%0,%1,%2,%3}, [%4];"
                 : "=r"(r0), "=r"(r1), "=r"(r2), "=r"(r3) : "r"(addr));
}
__device__ __forceinline__ void mma16816(float* c, const uint32_t* a, const uint32_t* b) {
    asm volatile("mma.sync.aligned.m16n8k16.row.col.f32.bf16.bf16.f32 "
                 "{%0,%1,%2,%3}, {%4,%5,%6,%7}, {%8,%9}, {%0,%1,%2,%3};"
                 : "+f"(c[0]), "+f"(c[1]), "+f"(c[2]), "+f"(c[3])
                 : "r"(a[0]), "r"(a[1]), "r"(a[2]), "r"(a[3]), "r"(b[0]), "r"(b[1]));
}
__device__ __forceinline__ void cvt_hilo(float4 v, uint2 &hp, uint2 &lp) {
    __nv_bfloat162 h0 = __float22bfloat162_rn(make_float2(v.x, v.y));
    __nv_bfloat162 h1 = __float22bfloat162_rn(make_float2(v.z, v.w));
    float2 f0 = __bfloat1622float2(h0), f1 = __bfloat1622float2(h1);
    __nv_bfloat162 l0 = __float22bfloat162_rn(make_float2(v.x - f0.x, v.y - f0.y));
    __nv_bfloat162 l1 = __float22bfloat162_rn(make_float2(v.z - f1.x, v.w - f1.y));
    hp = make_uint2(*(uint32_t*)&h0, *(uint32_t*)&h1);
    lp = make_uint2(*(uint32_t*)&l0, *(uint32_t*)&l1);
}

// Scratch: layer-0 input projection, [B*T, 96]
__device__ float g_xproj[(size_t)B_DIM * T_DIM * H_DIM];

// ===========================================================================
// Kernel 1: xproj = x @ w_ih0^T + b_ih0, HMMA bf16 3-split.
// CTA: 256 thr = 8 warps; tile M=256 x N=96; warp tile 64x48 (4x6 m16n8).
// K chunk = 32 (two k16 steps). Smem rows padded to 80B (bank-conflict-free
// ldmatrix: 80/4=20, 8 rows hit 8 distinct bank-groups mod 32).
// Register-staged chunk lookahead; 2 barriers / chunk.
// ===========================================================================
#define ROWB 80
#define SM_BIAS 0
#define SM_AHI  512
#define SM_ALO  (512 + 20480)
#define SM_BHI  (512 + 40960)
#define SM_BLO  (512 + 40960 + 7680)
#define GEMM_SMEM (512 + 40960 + 15360)   // 56832 bytes

__global__ __launch_bounds__(256, 1) void xproj_gemm(const float* __restrict__ X,
                                                     const float* __restrict__ W,
                                                     const float* __restrict__ bias)
{
    extern __shared__ char smem[];
    float* sbias = (float*)(smem + SM_BIAS);
    const int tid = threadIdx.x, lane = tid & 31, warp = tid >> 5;
    const int rowbase = blockIdx.x * 256;
    const int m_warp = (warp & 3) * 64;
    const int n_warp = (warp >> 2) * 48;

    if (tid < H_DIM) sbias[tid] = __ldg(bias + tid);

    // ldmatrix per-lane offset: groups g=lane>>3: (g&1)->row+8, (g>>1)->k half (+16B)
    const int g = lane >> 3, r = lane & 7;
    const uint32_t lane_off = (uint32_t)((((g & 1) << 3) + r) * ROWB + ((g >> 1) << 4));
    const uint32_t sb = smem_u32(smem);
    const uint32_t aHiB = sb + SM_AHI + (uint32_t)m_warp * ROWB + lane_off;
    const uint32_t aLoB = sb + SM_ALO + (uint32_t)m_warp * ROWB + lane_off;
    const uint32_t bHiB = sb + SM_BHI + (uint32_t)n_warp * ROWB + lane_off;
    const uint32_t bLoB = sb + SM_BLO + (uint32_t)n_warp * ROWB + lane_off;

    float acc[4][6][4];
    #pragma unroll
    for (int mt = 0; mt < 4; mt++)
        #pragma unroll
        for (int nt = 0; nt < 6; nt++)
            #pragma unroll
            for (int i = 0; i < 4; i++) acc[mt][nt][i] = 0.f;

    float4 sa[8], sw[3];

    auto load_stage = [&](int k0) {
        #pragma unroll
        for (int it = 0; it < 8; ++it) {
            int f = tid + it * 256;
            sa[it] = *(const float4*)(X + (size_t)(rowbase + (f >> 3)) * I_DIM + k0 + ((f & 7) << 2));
        }
        #pragma unroll
        for (int it = 0; it < 3; ++it) {
            int f = tid + it * 256;
            sw[it] = *(const float4*)(W + (size_t)(f >> 3) * I_DIM + k0 + ((f & 7) << 2));
        }
    };
    auto store_stage = [&]() {
        #pragma unroll
        for (int it = 0; it < 8; ++it) {
            int f = tid + it * 256;
            int off = (f >> 3) * ROWB + ((f & 7) << 3);
            uint2 hp, lp; cvt_hilo(sa[it], hp, lp);
            *(uint2*)(smem + SM_AHI + off) = hp;
            *(uint2*)(smem + SM_ALO + off) = lp;
        }
        #pragma unroll
        for (int it = 0; it < 3; ++it) {
            int f = tid + it * 256;
            int off = (f >> 3) * ROWB + ((f & 7) << 3);
            uint2 hp, lp; cvt_hilo(sw[it], hp, lp);
            *(uint2*)(smem + SM_BHI + off) = hp;
            *(uint2*)(smem + SM_BLO + off) = lp;
        }
    };

    load_stage(0);
    store_stage();
    __syncthreads();

    const int NC = I_DIM / 32;   // 64
    for (int c = 0; c < NC; ++c) {
        if (c + 1 < NC) load_stage((c + 1) * 32);

        #pragma unroll
        for (int s = 0; s < 2; ++s) {
            uint32_t ah[4][4], al[4][4], bh[6][2], bl[6][2];
            #pragma unroll
            for (int mt = 0; mt < 4; ++mt) {
                ldsm_x4(ah[mt][0], ah[mt][1], ah[mt][2], ah[mt][3], aHiB + mt * (16 * ROWB) + s * 32);
                ldsm_x4(al[mt][0], al[mt][1], al[mt][2], al[mt][3], aLoB + mt * (16 * ROWB) + s * 32);
            }
            #pragma unroll
            for (int np = 0; np < 3; ++np) {
                uint32_t r0, r1, r2, r3;
                ldsm_x4(r0, r1, r2, r3, bHiB + np * (16 * ROWB) + s * 32);
                bh[2 * np][0] = r0; bh[2 * np + 1][0] = r1;
                bh[2 * np][1] = r2; bh[2 * np + 1][1] = r3;
                ldsm_x4(r0, r1, r2, r3, bLoB + np * (16 * ROWB) + s * 32);
                bl[2 * np][0] = r0; bl[2 * np + 1][0] = r1;
                bl[2 * np][1] = r2; bl[2 * np + 1][1] = r3;
            }
            #pragma unroll
            for (int mt = 0; mt < 4; ++mt)
                #pragma unroll
                for (int nt = 0; nt < 6; ++nt) {
                    mma16816(acc[mt][nt], ah[mt], bh[nt]);
                    mma16816(acc[mt][nt], ah[mt], bl[nt]);
                    mma16816(acc[mt][nt], al[mt], bh[nt]);
                }
        }
        __syncthreads();
        if (c + 1 < NC) { store_stage(); }
        __syncthreads();
    }

    // Epilogue: add bias, write fp32 rows to g_xproj
    #pragma unroll
    for (int nt = 0; nt < 6; ++nt) {
        int col = n_warp + nt * 8 + (lane & 3) * 2;
        float b0 = sbias[col], b1 = sbias[col + 1];
        #pragma unroll
        for (int mt = 0; mt < 4; ++mt) {
            int row0 = rowbase + m_warp + mt * 16 + (lane >> 2);
            float2 v0 = make_float2(acc[mt][nt][0] + b0, acc[mt][nt][1] + b1);
            float2 v1 = make_float2(acc[mt][nt][2] + b0, acc[mt][nt][3] + b1);
            *(float2*)(g_xproj + (size_t)row0 * H_DIM + col) = v0;
            *(float2*)(g_xproj + (size_t)(row0 + 8) * H_DIM + col) = v1;
        }
    }
}

// ===========================================================================
// Kernel 2: recurrent scan, 1 CTA / batch, 3-layer wavefront, ONE barrier/tick.
// 480 threads = 15 warps:
//   tid 0-95:    layer0, full-K 96 dot (whh0 row j)
//   tid 96-287:  layer1, j = w*16+(lane&15), K-half = lane>>4,
//                combine via shfl_xor(16), lanes<16 write h1
//   tid 288-479: layer2, same pattern
// Weights in registers. h vectors double-buffered (parity) in smem.
// ===========================================================================
__global__ __launch_bounds__(480, 1) void rnn_scan(
    const float* __restrict__ whh0, const float* __restrict__ bhh0,
    const float* __restrict__ wih1, const float* __restrict__ whh1,
    const float* __restrict__ bih1, const float* __restrict__ bhh1,
    const float* __restrict__ wih2, const float* __restrict__ whh2,
    const float* __restrict__ bih2, const float* __restrict__ bhh2,
    const float* __restrict__ fcw,  const float* __restrict__ fcb,
    float* __restrict__ out)
{
    __shared__ __align__(16) float h0[2][96];
    __shared__ __align__(16) float h1[2][96];
    __shared__ __align__(16) float h2[2][96];
    __shared__ float sred[96];

    const int tid = threadIdx.x;
    const int lane = tid & 31;
    const int b = blockIdx.x;

    if (tid < 96) {
        h0[0][tid] = 0.f; h0[1][tid] = 0.f;
        h1[0][tid] = 0.f; h1[1][tid] = 0.f;
        h2[0][tid] = 0.f; h2[1][tid] = 0.f;
    }

    ull wA[24], wB[24];
    float bias = 0.f;
    int role, j, base = 0;
    if (tid < 96) {
        role = 0; j = tid;
        const float* rr = whh0 + j * 96;
        #pragma unroll
        for (int q = 0; q < 24; q++) wA[q] = pack2(__ldg(rr + 2 * q), __ldg(rr + 2 * q + 1));
        #pragma unroll
        for (int q = 0; q < 24; q++) wB[q] = pack2(__ldg(rr + 48 + 2 * q), __ldg(rr + 48 + 2 * q + 1));
        bias = __ldg(bhh0 + j);
    } else if (tid < 288) {
        role = 1;
        int w = (tid - 96) >> 5;
        j = w * 16 + (lane & 15);
        base = (lane >> 4) * 48;
        const float* ri = wih1 + j * 96 + base;
        const float* rh = whh1 + j * 96 + base;
        #pragma unroll
        for (int q = 0; q < 24; q++) wA[q] = pack2(__ldg(ri + 2 * q), __ldg(ri + 2 * q + 1));
        #pragma unroll
        for (int q = 0; q < 24; q++) wB[q] = pack2(__ldg(rh + 2 * q), __ldg(rh + 2 * q + 1));
        bias = __ldg(bih1 + j) + __ldg(bhh1 + j);
    } else {
        role = 2;
        int w = (tid - 288) >> 5;
        j = w * 16 + (lane & 15);
        base = (lane >> 4) * 48;
        const float* ri = wih2 + j * 96 + base;
        const float* rh = whh2 + j * 96 + base;
        #pragma unroll
        for (int q = 0; q < 24; q++) wA[q] = pack2(__ldg(ri + 2 * q), __ldg(ri + 2 * q + 1));
        #pragma unroll
        for (int q = 0; q < 24; q++) wB[q] = pack2(__ldg(rh + 2 * q), __ldg(rh + 2 * q + 1));
        bias = __ldg(bih2 + j) + __ldg(bhh2 + j);
    }

    const float* xpp = g_xproj + ((size_t)b * T_DIM) * H_DIM + j;
    float xp = (role == 0) ? __ldg(xpp) : 0.f;

    __syncthreads();

    for (int u = 0; u < T_DIM + 2; ++u) {
        const int p = u & 1, q = p ^ 1;
        const float *sa, *sb;
        bool act;
        if (role == 0)      { act = (u < T_DIM);                sa = h0[q];        sb = h0[q] + 48;   }
        else if (role == 1) { act = (u >= 1 && u <= T_DIM);     sa = h0[q] + base; sb = h1[p] + base; }
        else                { act = (u >= 2 && u <= T_DIM + 1); sa = h1[p] + base; sb = h2[q] + base; }

        if (act) {
            ull a0 = 0, a1 = 0, a2 = 0, a3 = 0;
            #pragma unroll
            for (int m = 0; m < 12; m++) {
                ulonglong2 va = *(const ulonglong2*)(sa + 4 * m);
                ulonglong2 vb = *(const ulonglong2*)(sb + 4 * m);
                fma2(a0, wA[2 * m],     va.x);
                fma2(a1, wA[2 * m + 1], va.y);
                fma2(a2, wB[2 * m],     vb.x);
                fma2(a3, wB[2 * m + 1], vb.y);
            }
            float s = (hadd2(a0) + hadd2(a1)) + (hadd2(a2) + hadd2(a3));
            if (role == 0) {
                h0[p][j] = fast_tanh(s + xp + bias);
                if (u + 1 < T_DIM) xp = xpp[(u + 1) * H_DIM];
            } else {
                s += __shfl_xor_sync(0xffffffffu, s, 16);
                if (lane < 16) {
                    float hv = fast_tanh(s + bias);
                    if (role == 1) h1[q][j] = hv;   // h1(u-1), parity (u-1)&1 == q
                    else           h2[p][j] = hv;   // h2(u-2), parity (u-2)&1 == p
                }
            }
        }
        __syncthreads();
    }

    // FC head: out[b] = h2(T-1) . fc_w + fc_b ; T-1=511 -> parity 1
    if (tid < 96) sred[tid] = h2[1][tid] * __ldg(fcw + tid);
    __syncthreads();
    if (tid == 0) {
        float s = __ldg(fcb);
        #pragma unroll
        for (int k = 0; k < 96; k++) s += sred[k];
        out[b] = s;
    }
}

extern "C" void kernel_launch(void* const* d_in, const int* in_sizes, int n_in,
                              void* d_out, int out_size) {
    const float* x     = (const float*)d_in[0];
    const float* w_ih0 = (const float*)d_in[1];
    const float* w_hh0 = (const float*)d_in[2];
    const float* b_ih0 = (const float*)d_in[3];
    const float* b_hh0 = (const float*)d_in[4];
    const float* w_ih1 = (const float*)d_in[5];
    const float* w_hh1 = (const float*)d_in[6];
    const float* b_ih1 = (const float*)d_in[7];
    const float* b_hh1 = (const float*)d_in[8];
    const float* w_ih2 = (const float*)d_in[9];
    const float* w_hh2 = (const float*)d_in[10];
    const float* b_ih2 = (const float*)d_in[11];
    const float* b_hh2 = (const float*)d_in[12];
    const float* fc_w  = (const float*)d_in[13];
    const float* fc_b  = (const float*)d_in[14];
    float* out = (float*)d_out;

    static bool attr_set = false;
    if (!attr_set) {
        cudaFuncSetAttribute(xproj_gemm, cudaFuncAttributeMaxDynamicSharedMemorySize, GEMM_SMEM);
        attr_set = true;
    }
    xproj_gemm<<<(B_DIM * T_DIM) / 256, 256, GEMM_SMEM>>>(x, w_ih0, b_ih0);
    rnn_scan<<<B_DIM, 480>>>(w_hh0, b_hh0,
                             w_ih1, w_hh1, b_ih1, b_hh1,
                             w_ih2, w_hh2, b_ih2, b_hh2,
                             fc_w, fc_b, out);
}